// round 14
// baseline (speedup 1.0000x reference)
#include <cuda_runtime.h>
#include <cuda_fp16.h>
#include <math.h>
#include <stdint.h>

// Fixed-shape problem: S=T=4, D=H=DT=128, N=65536
#define NS 4
#define NT 4
#define DK 128
#define NMAX 65536
#define TM 128
#define NTH 512                  // 16 warps, 4/SMSP; de-fused passes keep regs < 128
#define CPB 38                   // CTAs per type (4*38 = 152 = GB300 SM count)
#define SBB 272                  // smem tile row stride in BYTES (136 fp16) — ldmatrix conflict-free
#define TILEB (128 * SBB)        // 34816 bytes per 128-row fp16 tile

// ---------------- device scratch (no allocations allowed) ----------------
__device__ int d_cursor[NS] = {0, 0, 0, 0};   // static-init zero; reset by last CTA
__device__ int d_barrier = 0;
__device__ int d_done = 0;
__device__ int d_perm[NS * NMAX];
// 4 experts x 3 mats (W1,C1,W2), fp16, packed Bt[n][k] 128x128 = 32KB each
__device__ __align__(16) unsigned char d_wbuf[4 * 3 * 32768];

// ---------------- helpers ----------------
__device__ __forceinline__ uint32_t smem_u32(const void* p) {
    uint32_t a;
    asm("{ .reg .u64 t; cvta.to.shared.u64 t, %1; cvt.u32.u64 %0, t; }"
        : "=r"(a) : "l"(p));
    return a;
}
__device__ __forceinline__ void ldsm4(uint32_t& r0, uint32_t& r1, uint32_t& r2,
                                      uint32_t& r3, uint32_t a) {
    asm volatile("ldmatrix.sync.aligned.m8n8.x4.shared.b16 {%0,%1,%2,%3}, [%4];"
                 : "=r"(r0), "=r"(r1), "=r"(r2), "=r"(r3) : "r"(a));
}
__device__ __forceinline__ void mma16816(float* d, const uint32_t* a,
                                         const uint32_t* b) {
    asm volatile(
        "mma.sync.aligned.m16n8k16.row.col.f32.f16.f16.f32 "
        "{%0,%1,%2,%3},{%4,%5,%6,%7},{%8,%9},{%0,%1,%2,%3};"
        : "+f"(d[0]), "+f"(d[1]), "+f"(d[2]), "+f"(d[3])
        : "r"(a[0]), "r"(a[1]), "r"(a[2]), "r"(a[3]), "r"(b[0]), "r"(b[1]));
}
// split fp32 pair -> (hi fp16x2, lo fp16x2)
__device__ __forceinline__ void split2h(float x0, float x1, uint32_t& hi, uint32_t& lo) {
    __half h0 = __float2half_rn(x0);
    __half h1 = __float2half_rn(x1);
    __half l0 = __float2half_rn(x0 - __half2float(h0));
    __half l1 = __float2half_rn(x1 - __half2float(h1));
    __half2 hp = __halves2half2(h0, h1);
    __half2 lp = __halves2half2(l0, l1);
    hi = *reinterpret_cast<uint32_t*>(&hp);
    lo = *reinterpret_cast<uint32_t*>(&lp);
}
// per-type argmax over T
__device__ __forceinline__ int best_of(const float* __restrict__ tm, int s, float& best) {
    best = tm[s * NT];
    int bt = 0;
#pragma unroll
    for (int t = 1; t < NT; t++) {
        float v = tm[s * NT + t];
        if (v > best) { best = v; bt = t; }
    }
    return bt;
}

// ============================================================
// SMEM layout (dynamic, bytes)
// ============================================================
static const int SM_B1S  = 0;
static const int SM_B2S  = 512;
static const int SM_C1B  = 1024;
static const int SM_C2V  = 1536;
static const int SM_CLS  = 2048;                // 4 x 128 floats
static const int SM_XHI  = 4096;
static const int SM_XLO  = SM_XHI + TILEB;
static const int SM_HH   = SM_XLO + TILEB;
static const int SM_W1   = SM_HH + TILEB;
static const int SM_C1W  = SM_W1 + TILEB;
static const int SM_W2   = SM_C1W + TILEB;
static const int SM_TOTAL = SM_W2 + TILEB;      // 212992 bytes (1 CTA/SM)

// copy one packed 32KB fp16 weight tile into a padded smem tile
__device__ __forceinline__ void copy_w(unsigned char* smem, int dstoff, int s, int m,
                                       int tid) {
    const uint4* src = (const uint4*)(d_wbuf + (size_t)(s * 3 + m) * 32768);
#pragma unroll
    for (int i = tid; i < 2048; i += NTH) {
        int row = i >> 4, c16 = i & 15;
        *(uint4*)(smem + dstoff + row * SBB + c16 * 16) = src[i];
    }
}

// gather one 128-row X tile -> fp16 hi/lo padded smem tiles (512 thr: 4/row)
__device__ __forceinline__ void gather_x(unsigned char* smem,
                                         const float* __restrict__ states,
                                         const int* __restrict__ perm, int rows,
                                         int tid) {
    int xr = tid >> 2, xq = tid & 3;     // 4 threads per row, 32 cols each
    bool valid = xr < rows;
    int g = valid ? perm[xr] : 0;
    const float4* src = (const float4*)(states + (size_t)g * DK + xq * 32);
    uint32_t base0 = xr * SBB + xq * 64;
#pragma unroll
    for (int j8 = 0; j8 < 4; j8++) {
        float4 a = valid ? src[j8 * 2] : make_float4(0, 0, 0, 0);
        float4 c = valid ? src[j8 * 2 + 1] : make_float4(0, 0, 0, 0);
        uint4 hi, lo;
        split2h(a.x, a.y, hi.x, lo.x);
        split2h(a.z, a.w, hi.y, lo.y);
        split2h(c.x, c.y, hi.z, lo.z);
        split2h(c.z, c.w, hi.w, lo.w);
        uint32_t off = base0 + j8 * 16;
        *(uint4*)(smem + SM_XHI + off) = hi;
        *(uint4*)(smem + SM_XLO + off) = lo;
    }
}

// ============================================================
// single persistent kernel: phase A (prep + scatter) -> device barrier ->
// phase B (type-pinned tile loop, resident weights, de-fused passes)
// ============================================================
__global__ __launch_bounds__(NTH, 1)
void mlp_kernel(const float* __restrict__ states,
                const float* __restrict__ scores,
                const int* __restrict__ tids,
                const float* __restrict__ tmatch,
                const float* __restrict__ W1g, const float* __restrict__ b1g,
                const float* __restrict__ W2g, const float* __restrict__ b2g,
                const float* __restrict__ C1g, const float* __restrict__ c1g,
                const float* __restrict__ C2g, const float* __restrict__ c2g,
                float* __restrict__ out, int n) {
    extern __shared__ unsigned char smem[];
    __shared__ int hh[NS], hbase[NS];
    int tid = threadIdx.x;

    // ================= Phase A =================
    // A1: weight prep on blocks 0..47 (e, m, quarter); 512 threads each
    if (blockIdx.x < 48) {
        int e = blockIdx.x / 12, rem = blockIdx.x % 12;
        int m = rem >> 2, q = rem & 3;
        float dummy;
        int sel = e * NT + best_of(tmatch, e, dummy);
        const float* src = (m == 0 ? W1g : (m == 1 ? C1g : W2g)) + (size_t)sel * 16384;
        unsigned char* dst = d_wbuf + (size_t)(e * 3 + m) * 32768;
#pragma unroll
        for (int i = 0; i < 8; i++) {
            int idx = q * 4096 + i * 512 + tid;
            float x = src[idx];
            int k = idx >> 7, nn = idx & 127;
            *(__half*)(dst + (uint32_t)(nn * 128 + k) * 2) = __float2half_rn(x);
        }
    }
    // A2: scatter — every block handles a contiguous chunk (chunk <= 512)
    {
        int chunk = (n + (int)gridDim.x - 1) / (int)gridDim.x;
        int i0 = blockIdx.x * chunk;
        int iend = min(i0 + chunk, n);
        if (tid < NS) hh[tid] = 0;
        __syncthreads();
        int i = i0 + tid;
        int ss = (tid < chunk && i < iend) ? tids[i] : -1;
        int rk = 0;
        if (ss >= 0) rk = atomicAdd(&hh[ss], 1);
        __syncthreads();
        if (tid < NS && hh[tid]) hbase[tid] = atomicAdd(&d_cursor[tid], hh[tid]);
        __syncthreads();
        if (ss >= 0) d_perm[ss * NMAX + hbase[ss] + rk] = i;
    }
    // device-wide barrier: all 152 CTAs co-resident (grid == SM count)
    __syncthreads();
    if (tid == 0) {
        __threadfence();
        atomicAdd(&d_barrier, 1);
        while (atomicAdd(&d_barrier, 0) < (int)gridDim.x) __nanosleep(64);
    }
    __syncthreads();

    // ================= Phase B =================
    int s = blockIdx.x / CPB;
    int cta = blockIdx.x - s * CPB;
    int cnt = d_cursor[s];

    int lane = tid & 31;
    int wid = tid >> 5;
    int wm = wid & 3, wn = wid >> 2;        // warp tile: rows 32*wm, cols 32*wn
    int gID = lane >> 2, tig = lane & 3;

    float* b1s = (float*)(smem + SM_B1S);
    float* b2s = (float*)(smem + SM_B2S);
    float* c1s = (float*)(smem + SM_C1B);
    float* c2v = (float*)(smem + SM_C2V);
    float* cls = (float*)(smem + SM_CLS);
    uint32_t Xhi = smem_u32(smem + SM_XHI), Xlo = smem_u32(smem + SM_XLO);
    uint32_t Hh = smem_u32(smem + SM_HH);
    uint32_t W1t = smem_u32(smem + SM_W1);
    uint32_t C1t = smem_u32(smem + SM_C1W);
    uint32_t W2t = smem_u32(smem + SM_W2);

    float bestlogit;
    int sel = s * NT + best_of(tmatch, s, bestlogit);
    float bprob = 1.0f / (1.0f + expf(-bestlogit));
    float c2sc = c2g[sel];

    if (cnt > 0 && cta * TM < cnt) {
        if (tid < DK) {
            b1s[tid] = b1g[sel * DK + tid];
            b2s[tid] = b2g[sel * DK + tid];
            c1s[tid] = c1g[sel * DK + tid];
            c2v[tid] = C2g[(size_t)sel * DK + tid];
        }
        // resident weights: load once
        copy_w(smem, SM_W1, s, 0, tid);
        copy_w(smem, SM_C1W, s, 1, tid);
        copy_w(smem, SM_W2, s, 2, tid);

        int tile = cta;
        int rows = min(TM, cnt - tile * TM);
        const int* perm = d_perm + s * NMAX + tile * TM;
        gather_x(smem, states, perm, rows, tid);
        __syncthreads();

        uint32_t a_row = (lane & 15);
        uint32_t a_c8 = (lane >> 4);
        uint32_t b_n = (lane & 7) + ((lane >> 4) << 3);
        uint32_t b_c8 = (lane >> 3) & 1;

        while (true) {
            int ntile = tile + CPB;
            int nrows = (ntile * TM < cnt) ? min(TM, cnt - ntile * TM) : 0;

            float acc[2][4][4];

            // ===== pass 1: D = (Xhi+Xlo) @ W1 =====
#pragma unroll
            for (int mt = 0; mt < 2; mt++)
#pragma unroll
                for (int ng = 0; ng < 4; ng++)
#pragma unroll
                    for (int i = 0; i < 4; i++) acc[mt][ng][i] = 0.f;
#pragma unroll
            for (int ks = 0; ks < 8; ks++) {
                uint32_t kb = ks * 32;
                uint32_t aoff = (wm * 32 + a_row) * SBB + kb + a_c8 * 16;
                uint32_t ah[2][4], al[2][4];
                ldsm4(ah[0][0], ah[0][1], ah[0][2], ah[0][3], Xhi + aoff);
                ldsm4(ah[1][0], ah[1][1], ah[1][2], ah[1][3], Xhi + aoff + 16 * SBB);
                ldsm4(al[0][0], al[0][1], al[0][2], al[0][3], Xlo + aoff);
                ldsm4(al[1][0], al[1][1], al[1][2], al[1][3], Xlo + aoff + 16 * SBB);
#pragma unroll
                for (int np = 0; np < 2; np++) {
                    uint32_t boff = (wn * 32 + np * 16 + b_n) * SBB + kb + b_c8 * 16;
                    uint32_t bw[4];
                    ldsm4(bw[0], bw[1], bw[2], bw[3], W1t + boff);
#pragma unroll
                    for (int mt = 0; mt < 2; mt++) {
#pragma unroll
                        for (int sb = 0; sb < 2; sb++) {
                            float* d = acc[mt][np * 2 + sb];
                            mma16816(d, ah[mt], bw + sb * 2);
                            mma16816(d, al[mt], bw + sb * 2);
                        }
                    }
                }
            }
            // epilogue 1: H = relu(D + b1) -> fp16 smem
#pragma unroll
            for (int mt = 0; mt < 2; mt++) {
#pragma unroll
                for (int rh = 0; rh < 2; rh++) {
                    int r = wm * 32 + mt * 16 + rh * 8 + gID;
                    uint32_t roff = r * SBB;
#pragma unroll
                    for (int ng = 0; ng < 4; ng++) {
                        int c = wn * 32 + ng * 8 + 2 * tig;
                        float v0 = fmaxf(acc[mt][ng][rh * 2 + 0] + b1s[c], 0.f);
                        float v1 = fmaxf(acc[mt][ng][rh * 2 + 1] + b1s[c + 1], 0.f);
                        __half2 hp = __halves2half2(__float2half_rn(v0), __float2half_rn(v1));
                        *(uint32_t*)(smem + SM_HH + roff + c * 2) =
                            *reinterpret_cast<uint32_t*>(&hp);
                    }
                }
            }

            // ===== pass 2: D = Xhi @ C1 (classifier, hi-only) =====
#pragma unroll
            for (int mt = 0; mt < 2; mt++)
#pragma unroll
                for (int ng = 0; ng < 4; ng++)
#pragma unroll
                    for (int i = 0; i < 4; i++) acc[mt][ng][i] = 0.f;
#pragma unroll
            for (int ks = 0; ks < 8; ks++) {
                uint32_t kb = ks * 32;
                uint32_t aoff = (wm * 32 + a_row) * SBB + kb + a_c8 * 16;
                uint32_t ah[2][4];
                ldsm4(ah[0][0], ah[0][1], ah[0][2], ah[0][3], Xhi + aoff);
                ldsm4(ah[1][0], ah[1][1], ah[1][2], ah[1][3], Xhi + aoff + 16 * SBB);
#pragma unroll
                for (int np = 0; np < 2; np++) {
                    uint32_t boff = (wn * 32 + np * 16 + b_n) * SBB + kb + b_c8 * 16;
                    uint32_t bw[4];
                    ldsm4(bw[0], bw[1], bw[2], bw[3], C1t + boff);
#pragma unroll
                    for (int mt = 0; mt < 2; mt++) {
#pragma unroll
                        for (int sb = 0; sb < 2; sb++)
                            mma16816(acc[mt][np * 2 + sb], ah[mt], bw + sb * 2);
                    }
                }
            }
            // epilogue 2: cls partials
#pragma unroll
            for (int mt = 0; mt < 2; mt++) {
#pragma unroll
                for (int rh = 0; rh < 2; rh++) {
                    int r = wm * 32 + mt * 16 + rh * 8 + gID;
                    float p = 0.f;
#pragma unroll
                    for (int ng = 0; ng < 4; ng++) {
                        int c = wn * 32 + ng * 8 + 2 * tig;
                        p += fmaxf(acc[mt][ng][rh * 2 + 0] + c1s[c], 0.f) * c2v[c];
                        p += fmaxf(acc[mt][ng][rh * 2 + 1] + c1s[c + 1], 0.f) * c2v[c + 1];
                    }
                    p += __shfl_xor_sync(0xffffffffu, p, 1);
                    p += __shfl_xor_sync(0xffffffffu, p, 2);
                    if (tig == 0) cls[wn * 128 + r] = p;
                }
            }
            __syncthreads();   // cls + H visible; all warps done reading X

            // scores / prob out
            if (tid < TM && tid < rows) {
                int g = perm[tid];
                float tot = cls[tid] + cls[128 + tid] + cls[256 + tid] +
                            cls[384 + tid] + c2sc;
                float cv = 1.0f / (1.0f + expf(-tot));
                float ns = fminf(scores[g], cv);
                out[(size_t)n * DK + g]     = ns;     // out_score
                out[(size_t)n * DK + n + g] = bprob;  // item_prob
            }

            // prefetch next tile's X (overlaps with pass 3)
            if (nrows > 0)
                gather_x(smem, states, d_perm + s * NMAX + ntile * TM, nrows, tid);

            // ===== pass 3: D = H @ W2 =====
#pragma unroll
            for (int mt = 0; mt < 2; mt++)
#pragma unroll
                for (int ng = 0; ng < 4; ng++)
#pragma unroll
                    for (int i = 0; i < 4; i++) acc[mt][ng][i] = 0.f;
#pragma unroll
            for (int ks = 0; ks < 8; ks++) {
                uint32_t kb = ks * 32;
                uint32_t aoff = (wm * 32 + a_row) * SBB + kb + a_c8 * 16;
                uint32_t ah[2][4];
                ldsm4(ah[0][0], ah[0][1], ah[0][2], ah[0][3], Hh + aoff);
                ldsm4(ah[1][0], ah[1][1], ah[1][2], ah[1][3], Hh + aoff + 16 * SBB);
#pragma unroll
                for (int np = 0; np < 2; np++) {
                    uint32_t boff = (wn * 32 + np * 16 + b_n) * SBB + kb + b_c8 * 16;
                    uint32_t bw[4];
                    ldsm4(bw[0], bw[1], bw[2], bw[3], W2t + boff);
#pragma unroll
                    for (int mt = 0; mt < 2; mt++) {
#pragma unroll
                        for (int sb = 0; sb < 2; sb++)
                            mma16816(acc[mt][np * 2 + sb], ah[mt], bw + sb * 2);
                    }
                }
            }
            // epilogue 3: out_state = D + b2
#pragma unroll
            for (int mt = 0; mt < 2; mt++) {
#pragma unroll
                for (int rh = 0; rh < 2; rh++) {
                    int r = wm * 32 + mt * 16 + rh * 8 + gID;
                    if (r < rows) {
                        int g = perm[r];
                        float* dst = out + (size_t)g * DK;
#pragma unroll
                        for (int ng = 0; ng < 4; ng++) {
                            int c = wn * 32 + ng * 8 + 2 * tig;
                            float2 v;
                            v.x = acc[mt][ng][rh * 2 + 0] + b2s[c];
                            v.y = acc[mt][ng][rh * 2 + 1] + b2s[c + 1];
                            *(float2*)(dst + c) = v;
                        }
                    }
                }
            }

            if (nrows <= 0) break;
            tile = ntile;
            rows = nrows;
            perm = d_perm + s * NMAX + tile * TM;
            __syncthreads();   // next X stores complete; H reads done before overwrite
        }
    }

    // ---- last CTA resets cursors + barrier for the next graph replay ----
    __syncthreads();
    if (tid == 0) {
        __threadfence();
        int old = atomicAdd(&d_done, 1);
        if (old == (int)gridDim.x - 1) {
            d_cursor[0] = 0; d_cursor[1] = 0; d_cursor[2] = 0; d_cursor[3] = 0;
            d_barrier = 0;
            d_done = 0;
            __threadfence();
        }
    }
}

// ============================================================
// launch
// ============================================================
extern "C" void kernel_launch(void* const* d_in, const int* in_sizes, int n_in,
                              void* d_out, int out_size) {
    const float* states = (const float*)d_in[0];
    const float* scores = (const float*)d_in[1];
    const int*   tids   = (const int*)d_in[2];
    const float* tmatch = (const float*)d_in[3];
    const float* W1 = (const float*)d_in[4];
    const float* b1 = (const float*)d_in[5];
    const float* W2 = (const float*)d_in[6];
    const float* b2 = (const float*)d_in[7];
    const float* C1 = (const float*)d_in[8];
    const float* c1 = (const float*)d_in[9];
    const float* C2 = (const float*)d_in[10];
    const float* c2 = (const float*)d_in[11];
    float* out = (float*)d_out;
    int n = in_sizes[2];

    cudaFuncSetAttribute(mlp_kernel, cudaFuncAttributeMaxDynamicSharedMemorySize, SM_TOTAL);

    mlp_kernel<<<NS * CPB, NTH, SM_TOTAL>>>(states, scores, tids, tmatch,
                                            W1, b1, W2, b2, C1, c1, C2, c2,
                                            out, n);
}

// round 15
// speedup vs baseline: 1.0705x; 1.0705x over previous
#include <cuda_runtime.h>
#include <cuda_fp16.h>
#include <math.h>
#include <stdint.h>

// Fixed-shape problem: S=T=4, D=H=DT=128, N=65536
#define NS 4
#define NT 4
#define DK 128
#define NMAX 65536
#define TM 128
#define NTH 256
#define CPB 38                   // CTAs per type (4*38 = 152 = GB300 SM count)
#define SBB 272                  // smem tile row stride in BYTES (136 fp16) — ldmatrix conflict-free
#define TILEB (128 * SBB)        // 34816 bytes per 128-row fp16 tile

// ---------------- device scratch (no allocations allowed) ----------------
__device__ int d_cursor[NS] = {0, 0, 0, 0};   // static-init zero; reset by last CTA
__device__ int d_barrier = 0;
__device__ int d_done = 0;
__device__ int d_perm[NS * NMAX];
// 4 experts x 3 mats (W1,C1,W2), fp16, packed Bt[n][k] 128x128 = 32KB each
__device__ __align__(16) unsigned char d_wbuf[4 * 3 * 32768];

// ---------------- helpers ----------------
__device__ __forceinline__ uint32_t smem_u32(const void* p) {
    uint32_t a;
    asm("{ .reg .u64 t; cvta.to.shared.u64 t, %1; cvt.u32.u64 %0, t; }"
        : "=r"(a) : "l"(p));
    return a;
}
__device__ __forceinline__ void ldsm4(uint32_t& r0, uint32_t& r1, uint32_t& r2,
                                      uint32_t& r3, uint32_t a) {
    asm volatile("ldmatrix.sync.aligned.m8n8.x4.shared.b16 {%0,%1,%2,%3}, [%4];"
                 : "=r"(r0), "=r"(r1), "=r"(r2), "=r"(r3) : "r"(a));
}
__device__ __forceinline__ void mma16816(float* d, const uint32_t* a,
                                         const uint32_t* b) {
    asm volatile(
        "mma.sync.aligned.m16n8k16.row.col.f32.f16.f16.f32 "
        "{%0,%1,%2,%3},{%4,%5,%6,%7},{%8,%9},{%0,%1,%2,%3};"
        : "+f"(d[0]), "+f"(d[1]), "+f"(d[2]), "+f"(d[3])
        : "r"(a[0]), "r"(a[1]), "r"(a[2]), "r"(a[3]), "r"(b[0]), "r"(b[1]));
}
// split fp32 pair -> (hi fp16x2, lo fp16x2)
__device__ __forceinline__ void split2h(float x0, float x1, uint32_t& hi, uint32_t& lo) {
    __half h0 = __float2half_rn(x0);
    __half h1 = __float2half_rn(x1);
    __half l0 = __float2half_rn(x0 - __half2float(h0));
    __half l1 = __float2half_rn(x1 - __half2float(h1));
    __half2 hp = __halves2half2(h0, h1);
    __half2 lp = __halves2half2(l0, l1);
    hi = *reinterpret_cast<uint32_t*>(&hp);
    lo = *reinterpret_cast<uint32_t*>(&lp);
}
// per-type argmax over T
__device__ __forceinline__ int best_of(const float* __restrict__ tm, int s, float& best) {
    best = tm[s * NT];
    int bt = 0;
#pragma unroll
    for (int t = 1; t < NT; t++) {
        float v = tm[s * NT + t];
        if (v > best) { best = v; bt = t; }
    }
    return bt;
}

// ============================================================
// SMEM layout (dynamic, bytes)
// ============================================================
static const int SM_B1S  = 0;
static const int SM_B2S  = 512;
static const int SM_C1B  = 1024;
static const int SM_C2V  = 1536;
static const int SM_CLS  = 2048;                // 2 x 128 floats
static const int SM_XHI  = 3072;
static const int SM_XLO  = SM_XHI + TILEB;
static const int SM_HH   = SM_XLO + TILEB;
static const int SM_W1   = SM_HH + TILEB;
static const int SM_C1W  = SM_W1 + TILEB;
static const int SM_W2   = SM_C1W + TILEB;
static const int SM_TOTAL = SM_W2 + TILEB;      // 211968 bytes (1 CTA/SM)

// copy one packed 32KB fp16 weight tile into a padded smem tile
__device__ __forceinline__ void copy_w(unsigned char* smem, int dstoff, int s, int m,
                                       int tid) {
    const uint4* src = (const uint4*)(d_wbuf + (size_t)(s * 3 + m) * 32768);
#pragma unroll
    for (int i = tid; i < 2048; i += NTH) {
        int row = i >> 4, c16 = i & 15;
        *(uint4*)(smem + dstoff + row * SBB + c16 * 16) = src[i];
    }
}

// gather one 128-row X tile -> fp16 hi/lo padded smem tiles
__device__ __forceinline__ void gather_x(unsigned char* smem,
                                         const float* __restrict__ states,
                                         const int* __restrict__ perm, int rows,
                                         int tid) {
    int xr = tid >> 1, xh = tid & 1;     // 2 threads/row, 64 cols each
    bool valid = xr < rows;
    int g = valid ? perm[xr] : 0;
    const float4* src = (const float4*)(states + (size_t)g * DK + xh * 64);
    uint32_t base0 = xr * SBB + xh * 128;
#pragma unroll
    for (int j8 = 0; j8 < 8; j8++) {
        float4 a = valid ? src[j8 * 2] : make_float4(0, 0, 0, 0);
        float4 c = valid ? src[j8 * 2 + 1] : make_float4(0, 0, 0, 0);
        uint4 hi, lo;
        split2h(a.x, a.y, hi.x, lo.x);
        split2h(a.z, a.w, hi.y, lo.y);
        split2h(c.x, c.y, hi.z, lo.z);
        split2h(c.z, c.w, hi.w, lo.w);
        uint32_t off = base0 + j8 * 16;
        *(uint4*)(smem + SM_XHI + off) = hi;
        *(uint4*)(smem + SM_XLO + off) = lo;
    }
}

// ============================================================
// single persistent kernel: phase A (prep + scatter) -> device barrier ->
// phase B (type-pinned tile loop, resident weights, B-frag pipelined)
// ============================================================
__global__ __launch_bounds__(NTH, 1)
void mlp_kernel(const float* __restrict__ states,
                const float* __restrict__ scores,
                const int* __restrict__ tids,
                const float* __restrict__ tmatch,
                const float* __restrict__ W1g, const float* __restrict__ b1g,
                const float* __restrict__ W2g, const float* __restrict__ b2g,
                const float* __restrict__ C1g, const float* __restrict__ c1g,
                const float* __restrict__ C2g, const float* __restrict__ c2g,
                float* __restrict__ out, int n) {
    extern __shared__ unsigned char smem[];
    __shared__ int hh[NS], hbase[NS];
    int tid = threadIdx.x;

    // ================= Phase A =================
    // A1: weight prep on blocks 0..47 (e, m, quarter)
    if (blockIdx.x < 48) {
        int e = blockIdx.x / 12, rem = blockIdx.x % 12;
        int m = rem >> 2, q = rem & 3;
        float dummy;
        int sel = e * NT + best_of(tmatch, e, dummy);
        const float* src = (m == 0 ? W1g : (m == 1 ? C1g : W2g)) + (size_t)sel * 16384;
        unsigned char* dst = d_wbuf + (size_t)(e * 3 + m) * 32768;
#pragma unroll 4
        for (int i = 0; i < 16; i++) {
            int idx = q * 4096 + i * 256 + tid;
            float x = src[idx];
            int k = idx >> 7, nn = idx & 127;
            *(__half*)(dst + (uint32_t)(nn * 128 + k) * 2) = __float2half_rn(x);
        }
    }
    // A2: scatter — every block handles a contiguous chunk
    {
        int chunk = (n + (int)gridDim.x - 1) / (int)gridDim.x;
        int i0 = blockIdx.x * chunk;
        int iend = min(i0 + chunk, n);
        if (tid < NS) hh[tid] = 0;
        __syncthreads();
        int ss[2], rk[2];
#pragma unroll
        for (int j = 0; j < 2; j++) {
            int i = i0 + j * NTH + tid;
            ss[j] = (i < iend) ? tids[i] : -1;
            if (ss[j] >= 0) rk[j] = atomicAdd(&hh[ss[j]], 1);
        }
        __syncthreads();
        if (tid < NS && hh[tid]) hbase[tid] = atomicAdd(&d_cursor[tid], hh[tid]);
        __syncthreads();
#pragma unroll
        for (int j = 0; j < 2; j++)
            if (ss[j] >= 0)
                d_perm[ss[j] * NMAX + hbase[ss[j]] + rk[j]] = i0 + j * NTH + tid;
    }
    // device-wide barrier: all 152 CTAs are co-resident (grid == SM count)
    __syncthreads();
    if (tid == 0) {
        __threadfence();
        atomicAdd(&d_barrier, 1);
        while (atomicAdd(&d_barrier, 0) < (int)gridDim.x) __nanosleep(64);
    }
    __syncthreads();

    // ================= Phase B =================
    int s = blockIdx.x / CPB;
    int cta = blockIdx.x - s * CPB;
    int cnt = d_cursor[s];

    int lane = tid & 31;
    int wid = tid >> 5;
    int wm = wid & 3, wn = wid >> 2;        // warp tile: rows 32*wm, cols 64*wn
    int gID = lane >> 2, tig = lane & 3;

    float* b1s = (float*)(smem + SM_B1S);
    float* b2s = (float*)(smem + SM_B2S);
    float* c1s = (float*)(smem + SM_C1B);
    float* c2v = (float*)(smem + SM_C2V);
    float* cls = (float*)(smem + SM_CLS);
    uint32_t Xhi = smem_u32(smem + SM_XHI), Xlo = smem_u32(smem + SM_XLO);
    uint32_t Hh = smem_u32(smem + SM_HH);
    uint32_t W1t = smem_u32(smem + SM_W1);
    uint32_t C1t = smem_u32(smem + SM_C1W);
    uint32_t W2t = smem_u32(smem + SM_W2);

    float bestlogit;
    int sel = s * NT + best_of(tmatch, s, bestlogit);
    float bprob = 1.0f / (1.0f + expf(-bestlogit));
    float c2sc = c2g[sel];

    if (cnt > 0 && cta * TM < cnt) {
        if (tid < DK) {
            b1s[tid] = b1g[sel * DK + tid];
            b2s[tid] = b2g[sel * DK + tid];
            c1s[tid] = c1g[sel * DK + tid];
            c2v[tid] = C2g[(size_t)sel * DK + tid];
        }
        // resident weights: load once
        copy_w(smem, SM_W1, s, 0, tid);
        copy_w(smem, SM_C1W, s, 1, tid);
        copy_w(smem, SM_W2, s, 2, tid);

        int tile = cta;
        int rows = min(TM, cnt - tile * TM);
        const int* perm = d_perm + s * NMAX + tile * TM;
        gather_x(smem, states, perm, rows, tid);
        __syncthreads();

        uint32_t a_row = (lane & 15);
        uint32_t a_c8 = (lane >> 4);
        uint32_t b_n = (lane & 7) + ((lane >> 4) << 3);
        uint32_t b_c8 = (lane >> 3) & 1;

        while (true) {
            int ntile = tile + CPB;
            int nrows = (ntile * TM < cnt) ? min(TM, cnt - ntile * TM) : 0;

            // ===== fused pass 1+2: D1 = (Xhi+Xlo)@W1, D2 = Xhi@C1 =====
            float acc1[2][8][4], acc2[2][8][4];
#pragma unroll
            for (int mt = 0; mt < 2; mt++)
#pragma unroll
                for (int ng = 0; ng < 8; ng++)
#pragma unroll
                    for (int i = 0; i < 4; i++) { acc1[mt][ng][i] = 0.f; acc2[mt][ng][i] = 0.f; }

#pragma unroll
            for (int ks = 0; ks < 8; ks++) {
                uint32_t kb = ks * 32;
                uint32_t aoff = (wm * 32 + a_row) * SBB + kb + a_c8 * 16;
                uint32_t ah[2][4], al[2][4];
                ldsm4(ah[0][0], ah[0][1], ah[0][2], ah[0][3], Xhi + aoff);
                ldsm4(ah[1][0], ah[1][1], ah[1][2], ah[1][3], Xhi + aoff + 16 * SBB);
                ldsm4(al[0][0], al[0][1], al[0][2], al[0][3], Xlo + aoff);
                ldsm4(al[1][0], al[1][1], al[1][2], al[1][3], Xlo + aoff + 16 * SBB);

                uint32_t bbase = (wn * 64 + b_n) * SBB + kb + b_c8 * 16;
                // double-buffered B fragments: preload np+1 before np's MMAs
                uint32_t bwA[4], bcA[4], bwB[4], bcB[4];
                ldsm4(bwA[0], bwA[1], bwA[2], bwA[3], W1t + bbase);
                ldsm4(bcA[0], bcA[1], bcA[2], bcA[3], C1t + bbase);
#pragma unroll
                for (int np = 0; np < 4; np++) {
                    const uint32_t* bw = (np & 1) ? bwB : bwA;
                    const uint32_t* bc = (np & 1) ? bcB : bcA;
                    uint32_t* bwn = (np & 1) ? bwA : bwB;
                    uint32_t* bcn = (np & 1) ? bcA : bcB;
                    if (np < 3) {
                        uint32_t bo = bbase + (uint32_t)(np + 1) * 16 * SBB;
                        ldsm4(bwn[0], bwn[1], bwn[2], bwn[3], W1t + bo);
                        ldsm4(bcn[0], bcn[1], bcn[2], bcn[3], C1t + bo);
                    }
                    // de-interleaved MMA groups (space dependent chains)
#pragma unroll
                    for (int mt = 0; mt < 2; mt++)
#pragma unroll
                        for (int sb = 0; sb < 2; sb++)
                            mma16816(acc1[mt][np * 2 + sb], ah[mt], bw + sb * 2);
#pragma unroll
                    for (int mt = 0; mt < 2; mt++)
#pragma unroll
                        for (int sb = 0; sb < 2; sb++)
                            mma16816(acc2[mt][np * 2 + sb], ah[mt], bc + sb * 2);
#pragma unroll
                    for (int mt = 0; mt < 2; mt++)
#pragma unroll
                        for (int sb = 0; sb < 2; sb++)
                            mma16816(acc1[mt][np * 2 + sb], al[mt], bw + sb * 2);
                }
            }

            // ===== epilogue 1+2: H = relu(D1+b1) -> fp16; cls partials from D2 =====
#pragma unroll
            for (int mt = 0; mt < 2; mt++) {
#pragma unroll
                for (int rh = 0; rh < 2; rh++) {
                    int r = wm * 32 + mt * 16 + rh * 8 + gID;
                    uint32_t roff = r * SBB;
                    float p = 0.f;
#pragma unroll
                    for (int ng = 0; ng < 8; ng++) {
                        int c = wn * 64 + ng * 8 + 2 * tig;
                        float v0 = fmaxf(acc1[mt][ng][rh * 2 + 0] + b1s[c], 0.f);
                        float v1 = fmaxf(acc1[mt][ng][rh * 2 + 1] + b1s[c + 1], 0.f);
                        __half2 hp = __halves2half2(__float2half_rn(v0), __float2half_rn(v1));
                        *(uint32_t*)(smem + SM_HH + roff + c * 2) =
                            *reinterpret_cast<uint32_t*>(&hp);
                        p += fmaxf(acc2[mt][ng][rh * 2 + 0] + c1s[c], 0.f) * c2v[c];
                        p += fmaxf(acc2[mt][ng][rh * 2 + 1] + c1s[c + 1], 0.f) * c2v[c + 1];
                    }
                    p += __shfl_xor_sync(0xffffffffu, p, 1);
                    p += __shfl_xor_sync(0xffffffffu, p, 2);
                    if (tig == 0) cls[wn * 128 + r] = p;
                }
            }
            __syncthreads();   // H + cls visible; all warps done reading X

            // scores / prob out
            if (tid < TM && tid < rows) {
                int g = perm[tid];
                float tot = cls[tid] + cls[128 + tid] + c2sc;
                float cv = 1.0f / (1.0f + expf(-tot));
                float ns = fminf(scores[g], cv);
                out[(size_t)n * DK + g]     = ns;     // out_score
                out[(size_t)n * DK + n + g] = bprob;  // item_prob
            }

            // prefetch next tile's X (overlaps with pass 3)
            if (nrows > 0)
                gather_x(smem, states, d_perm + s * NMAX + ntile * TM, nrows, tid);

            // ===== pass 3: D = H @ W2 (B-frag pipelined) =====
#pragma unroll
            for (int mt = 0; mt < 2; mt++)
#pragma unroll
                for (int ng = 0; ng < 8; ng++)
#pragma unroll
                    for (int i = 0; i < 4; i++) acc1[mt][ng][i] = 0.f;
#pragma unroll
            for (int ks = 0; ks < 8; ks++) {
                uint32_t kb = ks * 32;
                uint32_t aoff = (wm * 32 + a_row) * SBB + kb + a_c8 * 16;
                uint32_t ah[2][4];
                ldsm4(ah[0][0], ah[0][1], ah[0][2], ah[0][3], Hh + aoff);
                ldsm4(ah[1][0], ah[1][1], ah[1][2], ah[1][3], Hh + aoff + 16 * SBB);

                uint32_t bbase = (wn * 64 + b_n) * SBB + kb + b_c8 * 16;
                uint32_t bwA[4], bwB[4];
                ldsm4(bwA[0], bwA[1], bwA[2], bwA[3], W2t + bbase);
#pragma unroll
                for (int np = 0; np < 4; np++) {
                    const uint32_t* bw = (np & 1) ? bwB : bwA;
                    uint32_t* bwn = (np & 1) ? bwA : bwB;
                    if (np < 3) {
                        uint32_t bo = bbase + (uint32_t)(np + 1) * 16 * SBB;
                        ldsm4(bwn[0], bwn[1], bwn[2], bwn[3], W2t + bo);
                    }
#pragma unroll
                    for (int mt = 0; mt < 2; mt++)
#pragma unroll
                        for (int sb = 0; sb < 2; sb++)
                            mma16816(acc1[mt][np * 2 + sb], ah[mt], bw + sb * 2);
                }
            }

            // ===== epilogue 3: out_state = D + b2 =====
#pragma unroll
            for (int mt = 0; mt < 2; mt++) {
#pragma unroll
                for (int rh = 0; rh < 2; rh++) {
                    int r = wm * 32 + mt * 16 + rh * 8 + gID;
                    if (r < rows) {
                        int g = perm[r];
                        float* dst = out + (size_t)g * DK;
#pragma unroll
                        for (int ng = 0; ng < 8; ng++) {
                            int c = wn * 64 + ng * 8 + 2 * tig;
                            float2 v;
                            v.x = acc1[mt][ng][rh * 2 + 0] + b2s[c];
                            v.y = acc1[mt][ng][rh * 2 + 1] + b2s[c + 1];
                            *(float2*)(dst + c) = v;
                        }
                    }
                }
            }

            if (nrows <= 0) break;
            tile = ntile;
            rows = nrows;
            perm = d_perm + s * NMAX + tile * TM;
            __syncthreads();   // next X stores complete; H reads done before overwrite
        }
    }

    // ---- last CTA resets cursors + barrier for the next graph replay ----
    __syncthreads();
    if (tid == 0) {
        __threadfence();
        int old = atomicAdd(&d_done, 1);
        if (old == (int)gridDim.x - 1) {
            d_cursor[0] = 0; d_cursor[1] = 0; d_cursor[2] = 0; d_cursor[3] = 0;
            d_barrier = 0;
            d_done = 0;
            __threadfence();
        }
    }
}

// ============================================================
// launch
// ============================================================
extern "C" void kernel_launch(void* const* d_in, const int* in_sizes, int n_in,
                              void* d_out, int out_size) {
    const float* states = (const float*)d_in[0];
    const float* scores = (const float*)d_in[1];
    const int*   tids   = (const int*)d_in[2];
    const float* tmatch = (const float*)d_in[3];
    const float* W1 = (const float*)d_in[4];
    const float* b1 = (const float*)d_in[5];
    const float* W2 = (const float*)d_in[6];
    const float* b2 = (const float*)d_in[7];
    const float* C1 = (const float*)d_in[8];
    const float* c1 = (const float*)d_in[9];
    const float* C2 = (const float*)d_in[10];
    const float* c2 = (const float*)d_in[11];
    float* out = (float*)d_out;
    int n = in_sizes[2];

    cudaFuncSetAttribute(mlp_kernel, cudaFuncAttributeMaxDynamicSharedMemorySize, SM_TOTAL);

    mlp_kernel<<<NS * CPB, NTH, SM_TOTAL>>>(states, scores, tids, tmatch,
                                            W1, b1, W2, b2, C1, c1, C2, c2,
                                            out, n);
}

// round 16
// speedup vs baseline: 1.2547x; 1.1720x over previous
#include <cuda_runtime.h>
#include <cuda_fp16.h>
#include <math.h>
#include <stdint.h>

// Fixed-shape problem: S=T=4, D=H=DT=128, N=65536
#define NS 4
#define NT 4
#define DK 128
#define NMAX 65536
#define TM 128
#define NTH 256
#define CPB 38                   // CTAs per type (4*38 = 152 = GB300 SM count)
#define SBB 272                  // smem tile row stride in BYTES (136 fp16) — ldmatrix conflict-free
#define TILEB (128 * SBB)        // 34816 bytes per 128-row fp16 tile

// ---------------- device scratch (no allocations allowed) ----------------
__device__ int d_cursor[NS] = {0, 0, 0, 0};   // static-init zero; reset by last CTA
__device__ int d_barrier = 0;
__device__ int d_done = 0;
__device__ int d_perm[NS * NMAX];
// 4 experts x 3 mats (W1,C1,W2), fp16, packed Bt[n][k] 128x128 = 32KB each
__device__ __align__(16) unsigned char d_wbuf[4 * 3 * 32768];

// ---------------- helpers ----------------
__device__ __forceinline__ uint32_t smem_u32(const void* p) {
    uint32_t a;
    asm("{ .reg .u64 t; cvta.to.shared.u64 t, %1; cvt.u32.u64 %0, t; }"
        : "=r"(a) : "l"(p));
    return a;
}
__device__ __forceinline__ void ldsm4(uint32_t& r0, uint32_t& r1, uint32_t& r2,
                                      uint32_t& r3, uint32_t a) {
    asm volatile("ldmatrix.sync.aligned.m8n8.x4.shared.b16 {%0,%1,%2,%3}, [%4];"
                 : "=r"(r0), "=r"(r1), "=r"(r2), "=r"(r3) : "r"(a));
}
__device__ __forceinline__ void mma16816(float* d, const uint32_t* a,
                                         const uint32_t* b) {
    asm volatile(
        "mma.sync.aligned.m16n8k16.row.col.f32.f16.f16.f32 "
        "{%0,%1,%2,%3},{%4,%5,%6,%7},{%8,%9},{%0,%1,%2,%3};"
        : "+f"(d[0]), "+f"(d[1]), "+f"(d[2]), "+f"(d[3])
        : "r"(a[0]), "r"(a[1]), "r"(a[2]), "r"(a[3]), "r"(b[0]), "r"(b[1]));
}
__device__ __forceinline__ uint32_t packh2(float x0, float x1) {
    __half2 hp = __floats2half2_rn(x0, x1);
    return *reinterpret_cast<uint32_t*>(&hp);
}
// per-type argmax over T
__device__ __forceinline__ int best_of(const float* __restrict__ tm, int s, float& best) {
    best = tm[s * NT];
    int bt = 0;
#pragma unroll
    for (int t = 1; t < NT; t++) {
        float v = tm[s * NT + t];
        if (v > best) { best = v; bt = t; }
    }
    return bt;
}

// ============================================================
// SMEM layout (dynamic, bytes)
// ============================================================
static const int SM_B1S  = 0;
static const int SM_B2S  = 512;
static const int SM_C1B  = 1024;
static const int SM_C2V  = 1536;
static const int SM_CLS  = 2048;                // 2 x 128 floats
static const int SM_XHI  = 3072;
static const int SM_HH   = SM_XHI + TILEB;
static const int SM_W1   = SM_HH + TILEB;
static const int SM_C1W  = SM_W1 + TILEB;
static const int SM_W2   = SM_C1W + TILEB;
static const int SM_TOTAL = SM_W2 + TILEB;      // 177152 bytes (1 CTA/SM)

// copy one packed 32KB fp16 weight tile into a padded smem tile
__device__ __forceinline__ void copy_w(unsigned char* smem, int dstoff, int s, int m,
                                       int tid) {
    const uint4* src = (const uint4*)(d_wbuf + (size_t)(s * 3 + m) * 32768);
#pragma unroll
    for (int i = tid; i < 2048; i += NTH) {
        int row = i >> 4, c16 = i & 15;
        *(uint4*)(smem + dstoff + row * SBB + c16 * 16) = src[i];
    }
}

// gather one 128-row X tile -> fp16 padded smem tile (single-rounded)
__device__ __forceinline__ void gather_x(unsigned char* smem,
                                         const float* __restrict__ states,
                                         const int* __restrict__ perm, int rows,
                                         int tid) {
    int xr = tid >> 1, xh = tid & 1;     // 2 threads/row, 64 cols each
    bool valid = xr < rows;
    int g = valid ? perm[xr] : 0;
    const float4* src = (const float4*)(states + (size_t)g * DK + xh * 64);
    uint32_t base0 = xr * SBB + xh * 128;
#pragma unroll
    for (int j8 = 0; j8 < 8; j8++) {
        float4 a = valid ? src[j8 * 2] : make_float4(0, 0, 0, 0);
        float4 c = valid ? src[j8 * 2 + 1] : make_float4(0, 0, 0, 0);
        uint4 hi;
        hi.x = packh2(a.x, a.y);
        hi.y = packh2(a.z, a.w);
        hi.z = packh2(c.x, c.y);
        hi.w = packh2(c.z, c.w);
        *(uint4*)(smem + SM_XHI + base0 + j8 * 16) = hi;
    }
}

// ============================================================
// single persistent kernel: phase A (prep + scatter) -> device barrier ->
// phase B (type-pinned tile loop, resident weights, 1-term fp16 GEMMs)
// ============================================================
__global__ __launch_bounds__(NTH, 1)
void mlp_kernel(const float* __restrict__ states,
                const float* __restrict__ scores,
                const int* __restrict__ tids,
                const float* __restrict__ tmatch,
                const float* __restrict__ W1g, const float* __restrict__ b1g,
                const float* __restrict__ W2g, const float* __restrict__ b2g,
                const float* __restrict__ C1g, const float* __restrict__ c1g,
                const float* __restrict__ C2g, const float* __restrict__ c2g,
                float* __restrict__ out, int n) {
    extern __shared__ unsigned char smem[];
    __shared__ int hh[NS], hbase[NS];
    int tid = threadIdx.x;

    // ================= Phase A =================
    // A1: weight prep on blocks 0..47 (e, m, quarter)
    if (blockIdx.x < 48) {
        int e = blockIdx.x / 12, rem = blockIdx.x % 12;
        int m = rem >> 2, q = rem & 3;
        float dummy;
        int sel = e * NT + best_of(tmatch, e, dummy);
        const float* src = (m == 0 ? W1g : (m == 1 ? C1g : W2g)) + (size_t)sel * 16384;
        unsigned char* dst = d_wbuf + (size_t)(e * 3 + m) * 32768;
#pragma unroll 4
        for (int i = 0; i < 16; i++) {
            int idx = q * 4096 + i * 256 + tid;
            float x = src[idx];
            int k = idx >> 7, nn = idx & 127;
            *(__half*)(dst + (uint32_t)(nn * 128 + k) * 2) = __float2half_rn(x);
        }
    }
    // A2: scatter — every block handles a contiguous chunk
    {
        int chunk = (n + (int)gridDim.x - 1) / (int)gridDim.x;
        int i0 = blockIdx.x * chunk;
        int iend = min(i0 + chunk, n);
        if (tid < NS) hh[tid] = 0;
        __syncthreads();
        int ss[2], rk[2];
#pragma unroll
        for (int j = 0; j < 2; j++) {
            int i = i0 + j * NTH + tid;
            ss[j] = (i < iend) ? tids[i] : -1;
            if (ss[j] >= 0) rk[j] = atomicAdd(&hh[ss[j]], 1);
        }
        __syncthreads();
        if (tid < NS && hh[tid]) hbase[tid] = atomicAdd(&d_cursor[tid], hh[tid]);
        __syncthreads();
#pragma unroll
        for (int j = 0; j < 2; j++)
            if (ss[j] >= 0)
                d_perm[ss[j] * NMAX + hbase[ss[j]] + rk[j]] = i0 + j * NTH + tid;
    }
    // device-wide barrier: all 152 CTAs are co-resident (grid == SM count)
    __syncthreads();
    if (tid == 0) {
        __threadfence();
        atomicAdd(&d_barrier, 1);
        while (atomicAdd(&d_barrier, 0) < (int)gridDim.x) __nanosleep(64);
    }
    __syncthreads();

    // ================= Phase B =================
    int s = blockIdx.x / CPB;
    int cta = blockIdx.x - s * CPB;
    int cnt = d_cursor[s];

    int lane = tid & 31;
    int wid = tid >> 5;
    int wm = wid & 3, wn = wid >> 2;        // warp tile: rows 32*wm, cols 64*wn
    int gID = lane >> 2, tig = lane & 3;

    float* b1s = (float*)(smem + SM_B1S);
    float* b2s = (float*)(smem + SM_B2S);
    float* c1s = (float*)(smem + SM_C1B);
    float* c2v = (float*)(smem + SM_C2V);
    float* cls = (float*)(smem + SM_CLS);
    uint32_t Xhi = smem_u32(smem + SM_XHI);
    uint32_t Hh = smem_u32(smem + SM_HH);
    uint32_t W1t = smem_u32(smem + SM_W1);
    uint32_t C1t = smem_u32(smem + SM_C1W);
    uint32_t W2t = smem_u32(smem + SM_W2);

    float bestlogit;
    int sel = s * NT + best_of(tmatch, s, bestlogit);
    float bprob = 1.0f / (1.0f + expf(-bestlogit));
    float c2sc = c2g[sel];

    if (cnt > 0 && cta * TM < cnt) {
        if (tid < DK) {
            b1s[tid] = b1g[sel * DK + tid];
            b2s[tid] = b2g[sel * DK + tid];
            c1s[tid] = c1g[sel * DK + tid];
            c2v[tid] = C2g[(size_t)sel * DK + tid];
        }
        // resident weights: load once
        copy_w(smem, SM_W1, s, 0, tid);
        copy_w(smem, SM_C1W, s, 1, tid);
        copy_w(smem, SM_W2, s, 2, tid);

        int tile = cta;
        int rows = min(TM, cnt - tile * TM);
        const int* perm = d_perm + s * NMAX + tile * TM;
        gather_x(smem, states, perm, rows, tid);
        __syncthreads();

        uint32_t a_row = (lane & 15);
        uint32_t a_c8 = (lane >> 4);
        uint32_t b_n = (lane & 7) + ((lane >> 4) << 3);
        uint32_t b_c8 = (lane >> 3) & 1;

        while (true) {
            int ntile = tile + CPB;
            int nrows = (ntile * TM < cnt) ? min(TM, cnt - ntile * TM) : 0;

            // ===== fused pass 1+2: D1 = X@W1, D2 = X@C1 (1-term fp16) =====
            float acc1[2][8][4], acc2[2][8][4];
#pragma unroll
            for (int mt = 0; mt < 2; mt++)
#pragma unroll
                for (int ng = 0; ng < 8; ng++)
#pragma unroll
                    for (int i = 0; i < 4; i++) { acc1[mt][ng][i] = 0.f; acc2[mt][ng][i] = 0.f; }

#pragma unroll
            for (int ks = 0; ks < 8; ks++) {
                uint32_t kb = ks * 32;
                uint32_t aoff = (wm * 32 + a_row) * SBB + kb + a_c8 * 16;
                uint32_t ah[2][4];
                ldsm4(ah[0][0], ah[0][1], ah[0][2], ah[0][3], Xhi + aoff);
                ldsm4(ah[1][0], ah[1][1], ah[1][2], ah[1][3], Xhi + aoff + 16 * SBB);

                uint32_t bbase = (wn * 64 + b_n) * SBB + kb + b_c8 * 16;
                // double-buffered B fragments: preload np+1 before np's MMAs
                uint32_t bwA[4], bcA[4], bwB[4], bcB[4];
                ldsm4(bwA[0], bwA[1], bwA[2], bwA[3], W1t + bbase);
                ldsm4(bcA[0], bcA[1], bcA[2], bcA[3], C1t + bbase);
#pragma unroll
                for (int np = 0; np < 4; np++) {
                    const uint32_t* bw = (np & 1) ? bwB : bwA;
                    const uint32_t* bc = (np & 1) ? bcB : bcA;
                    uint32_t* bwn = (np & 1) ? bwA : bwB;
                    uint32_t* bcn = (np & 1) ? bcA : bcB;
                    if (np < 3) {
                        uint32_t bo = bbase + (uint32_t)(np + 1) * 16 * SBB;
                        ldsm4(bwn[0], bwn[1], bwn[2], bwn[3], W1t + bo);
                        ldsm4(bcn[0], bcn[1], bcn[2], bcn[3], C1t + bo);
                    }
#pragma unroll
                    for (int mt = 0; mt < 2; mt++)
#pragma unroll
                        for (int sb = 0; sb < 2; sb++)
                            mma16816(acc1[mt][np * 2 + sb], ah[mt], bw + sb * 2);
#pragma unroll
                    for (int mt = 0; mt < 2; mt++)
#pragma unroll
                        for (int sb = 0; sb < 2; sb++)
                            mma16816(acc2[mt][np * 2 + sb], ah[mt], bc + sb * 2);
                }
            }

            // ===== epilogue 1+2: H = relu(D1+b1) -> fp16; cls partials from D2 =====
#pragma unroll
            for (int mt = 0; mt < 2; mt++) {
#pragma unroll
                for (int rh = 0; rh < 2; rh++) {
                    int r = wm * 32 + mt * 16 + rh * 8 + gID;
                    uint32_t roff = r * SBB;
                    float p = 0.f;
#pragma unroll
                    for (int ng = 0; ng < 8; ng++) {
                        int c = wn * 64 + ng * 8 + 2 * tig;
                        float v0 = fmaxf(acc1[mt][ng][rh * 2 + 0] + b1s[c], 0.f);
                        float v1 = fmaxf(acc1[mt][ng][rh * 2 + 1] + b1s[c + 1], 0.f);
                        *(uint32_t*)(smem + SM_HH + roff + c * 2) = packh2(v0, v1);
                        p += fmaxf(acc2[mt][ng][rh * 2 + 0] + c1s[c], 0.f) * c2v[c];
                        p += fmaxf(acc2[mt][ng][rh * 2 + 1] + c1s[c + 1], 0.f) * c2v[c + 1];
                    }
                    p += __shfl_xor_sync(0xffffffffu, p, 1);
                    p += __shfl_xor_sync(0xffffffffu, p, 2);
                    if (tig == 0) cls[wn * 128 + r] = p;
                }
            }
            __syncthreads();   // H + cls visible; all warps done reading X

            // scores / prob out
            if (tid < TM && tid < rows) {
                int g = perm[tid];
                float tot = cls[tid] + cls[128 + tid] + c2sc;
                float cv = 1.0f / (1.0f + expf(-tot));
                float ns = fminf(scores[g], cv);
                out[(size_t)n * DK + g]     = ns;     // out_score
                out[(size_t)n * DK + n + g] = bprob;  // item_prob
            }

            // prefetch next tile's X (overlaps with pass 3)
            if (nrows > 0)
                gather_x(smem, states, d_perm + s * NMAX + ntile * TM, nrows, tid);

            // ===== pass 3: D = H @ W2 (B-frag pipelined) =====
#pragma unroll
            for (int mt = 0; mt < 2; mt++)
#pragma unroll
                for (int ng = 0; ng < 8; ng++)
#pragma unroll
                    for (int i = 0; i < 4; i++) acc1[mt][ng][i] = 0.f;
#pragma unroll
            for (int ks = 0; ks < 8; ks++) {
                uint32_t kb = ks * 32;
                uint32_t aoff = (wm * 32 + a_row) * SBB + kb + a_c8 * 16;
                uint32_t ah[2][4];
                ldsm4(ah[0][0], ah[0][1], ah[0][2], ah[0][3], Hh + aoff);
                ldsm4(ah[1][0], ah[1][1], ah[1][2], ah[1][3], Hh + aoff + 16 * SBB);

                uint32_t bbase = (wn * 64 + b_n) * SBB + kb + b_c8 * 16;
                uint32_t bwA[4], bwB[4];
                ldsm4(bwA[0], bwA[1], bwA[2], bwA[3], W2t + bbase);
#pragma unroll
                for (int np = 0; np < 4; np++) {
                    const uint32_t* bw = (np & 1) ? bwB : bwA;
                    uint32_t* bwn = (np & 1) ? bwA : bwB;
                    if (np < 3) {
                        uint32_t bo = bbase + (uint32_t)(np + 1) * 16 * SBB;
                        ldsm4(bwn[0], bwn[1], bwn[2], bwn[3], W2t + bo);
                    }
#pragma unroll
                    for (int mt = 0; mt < 2; mt++)
#pragma unroll
                        for (int sb = 0; sb < 2; sb++)
                            mma16816(acc1[mt][np * 2 + sb], ah[mt], bw + sb * 2);
                }
            }

            // ===== epilogue 3: out_state = D + b2 =====
#pragma unroll
            for (int mt = 0; mt < 2; mt++) {
#pragma unroll
                for (int rh = 0; rh < 2; rh++) {
                    int r = wm * 32 + mt * 16 + rh * 8 + gID;
                    if (r < rows) {
                        int g = perm[r];
                        float* dst = out + (size_t)g * DK;
#pragma unroll
                        for (int ng = 0; ng < 8; ng++) {
                            int c = wn * 64 + ng * 8 + 2 * tig;
                            float2 v;
                            v.x = acc1[mt][ng][rh * 2 + 0] + b2s[c];
                            v.y = acc1[mt][ng][rh * 2 + 1] + b2s[c + 1];
                            *(float2*)(dst + c) = v;
                        }
                    }
                }
            }

            if (nrows <= 0) break;
            tile = ntile;
            rows = nrows;
            perm = d_perm + s * NMAX + tile * TM;
            __syncthreads();   // next X stores complete; H reads done before overwrite
        }
    }

    // ---- last CTA resets cursors + barrier for the next graph replay ----
    __syncthreads();
    if (tid == 0) {
        __threadfence();
        int old = atomicAdd(&d_done, 1);
        if (old == (int)gridDim.x - 1) {
            d_cursor[0] = 0; d_cursor[1] = 0; d_cursor[2] = 0; d_cursor[3] = 0;
            d_barrier = 0;
            d_done = 0;
            __threadfence();
        }
    }
}

// ============================================================
// launch
// ============================================================
extern "C" void kernel_launch(void* const* d_in, const int* in_sizes, int n_in,
                              void* d_out, int out_size) {
    const float* states = (const float*)d_in[0];
    const float* scores = (const float*)d_in[1];
    const int*   tids   = (const int*)d_in[2];
    const float* tmatch = (const float*)d_in[3];
    const float* W1 = (const float*)d_in[4];
    const float* b1 = (const float*)d_in[5];
    const float* W2 = (const float*)d_in[6];
    const float* b2 = (const float*)d_in[7];
    const float* C1 = (const float*)d_in[8];
    const float* c1 = (const float*)d_in[9];
    const float* C2 = (const float*)d_in[10];
    const float* c2 = (const float*)d_in[11];
    float* out = (float*)d_out;
    int n = in_sizes[2];

    cudaFuncSetAttribute(mlp_kernel, cudaFuncAttributeMaxDynamicSharedMemorySize, SM_TOTAL);

    mlp_kernel<<<NS * CPB, NTH, SM_TOTAL>>>(states, scores, tids, tmatch,
                                            W1, b1, W2, b2, C1, c1, C2, c2,
                                            out, n);
}